// round 1
// baseline (speedup 1.0000x reference)
#include <cuda_runtime.h>
#include <math.h>

// Problem constants
#define TOK   8192          // B*S
#define DMODEL 512
#define SQ    2048
#define NHEADS 8
#define HDIM  64
#define WIN   5

// ---------------------------------------------------------------------------
// Device scratch (static allocations, allowed by harness rules)
// ---------------------------------------------------------------------------
__device__ float g_h1[(size_t)TOK * 1024];   // MLP hidden
__device__ float g_xm[(size_t)TOK * DMODEL]; // MLP output
__device__ float g_q [(size_t)TOK * DMODEL];
__device__ float g_k [(size_t)TOK * DMODEL];
__device__ float g_v [(size_t)TOK * DMODEL];
__device__ float g_o [(size_t)TOK * DMODEL]; // attention output (pre out-proj)

// ---------------------------------------------------------------------------
// Generic SGEMM: C[M,N] = act(A[M,K] @ B[K,N] + bias[N])
// BM=128, BN=64, BK=16, 256 threads, each thread computes 8x4.
// Requires M%128==0, N%64==0, K%16==0 (true for all calls here).
// ---------------------------------------------------------------------------
template<int RELU>
__global__ __launch_bounds__(256) void gemm_kernel(
    const float* __restrict__ A, const float* __restrict__ B,
    const float* __restrict__ bias, float* __restrict__ C,
    int M, int N, int K)
{
    __shared__ float As[16][128];   // transposed A tile: As[k][m]
    __shared__ float Bs[16][64];

    const int tid = threadIdx.x;
    const int m0  = blockIdx.y * 128;
    const int n0  = blockIdx.x * 64;
    const int ty  = tid >> 4;       // 0..15 -> 8 rows each
    const int tx  = tid & 15;       // 0..15 -> 4 cols each

    float acc[8][4];
#pragma unroll
    for (int i = 0; i < 8; i++)
#pragma unroll
        for (int j = 0; j < 4; j++) acc[i][j] = 0.f;

    for (int k0 = 0; k0 < K; k0 += 16) {
        // Load A tile 128x16 (2 float4 per thread), store transposed
#pragma unroll
        for (int t = 0; t < 2; t++) {
            int idx = tid + t * 256;          // 0..511
            int r   = idx >> 2;               // 0..127
            int c4  = (idx & 3) << 2;         // 0,4,8,12
            float4 v = *(const float4*)(A + (size_t)(m0 + r) * K + k0 + c4);
            As[c4 + 0][r] = v.x;
            As[c4 + 1][r] = v.y;
            As[c4 + 2][r] = v.z;
            As[c4 + 3][r] = v.w;
        }
        // Load B tile 16x64 (1 float4 per thread)
        {
            int r  = tid >> 4;                // 0..15
            int c4 = (tid & 15) << 2;         // 0..60
            float4 v = *(const float4*)(B + (size_t)(k0 + r) * N + n0 + c4);
            *(float4*)&Bs[r][c4] = v;
        }
        __syncthreads();

#pragma unroll
        for (int kk = 0; kk < 16; kk++) {
            float a[8], bv[4];
#pragma unroll
            for (int i = 0; i < 8; i++) a[i] = As[kk][ty * 8 + i];
#pragma unroll
            for (int j = 0; j < 4; j++) bv[j] = Bs[kk][tx * 4 + j];
#pragma unroll
            for (int i = 0; i < 8; i++)
#pragma unroll
                for (int j = 0; j < 4; j++)
                    acc[i][j] += a[i] * bv[j];
        }
        __syncthreads();
    }

    // Epilogue: bias (+ReLU), vectorized store
    float4 bj = *(const float4*)(bias + n0 + tx * 4);
#pragma unroll
    for (int i = 0; i < 8; i++) {
        float4 c;
        c.x = acc[i][0] + bj.x;
        c.y = acc[i][1] + bj.y;
        c.z = acc[i][2] + bj.z;
        c.w = acc[i][3] + bj.w;
        if (RELU) {
            c.x = fmaxf(c.x, 0.f); c.y = fmaxf(c.y, 0.f);
            c.z = fmaxf(c.z, 0.f); c.w = fmaxf(c.w, 0.f);
        }
        *(float4*)(C + (size_t)(m0 + ty * 8 + i) * N + n0 + tx * 4) = c;
    }
}

// ---------------------------------------------------------------------------
// Flash-attention with INVERSE sliding-window mask (|i-j| <= WIN excluded).
// Q/K/V in [B,S,d] layout; head h occupies columns h*64..h*64+63.
// One block: 64-query tile for one (b,h). 256 threads, 4x4 blocking.
// Dynamic smem: Qs/Ks/Vs/Ps each [64][65] floats.
// ---------------------------------------------------------------------------
__global__ __launch_bounds__(256) void attn_kernel(
    const float* __restrict__ Qg, const float* __restrict__ Kg,
    const float* __restrict__ Vg, float* __restrict__ Og)
{
    extern __shared__ float sm[];
    float* Qs = sm;                   // [64][65]
    float* Ks = Qs + 64 * 65;
    float* Vs = Ks + 64 * 65;
    float* Ps = Vs + 64 * 65;

    const int bh = blockIdx.y;
    const int b  = bh >> 3;
    const int h  = bh & 7;
    const int q0 = blockIdx.x * 64;
    const int tid = threadIdx.x;
    const int ty = tid >> 4;          // 0..15 -> 4 rows each
    const int tx = tid & 15;          // 0..15 -> 4 cols each

    const float* Qb = Qg + (size_t)b * SQ * DMODEL + h * HDIM;
    const float* Kb = Kg + (size_t)b * SQ * DMODEL + h * HDIM;
    const float* Vb = Vg + (size_t)b * SQ * DMODEL + h * HDIM;

    // Load Q tile (64 rows x 64 floats), 4 float4 per thread
    for (int i = tid; i < 64 * 16; i += 256) {
        int r  = i >> 4;
        int c4 = (i & 15) << 2;
        float4 v = *(const float4*)(Qb + (size_t)(q0 + r) * DMODEL + c4);
        Qs[r * 65 + c4 + 0] = v.x;
        Qs[r * 65 + c4 + 1] = v.y;
        Qs[r * 65 + c4 + 2] = v.z;
        Qs[r * 65 + c4 + 3] = v.w;
    }

    float o[4][4];
    float mrow[4], lrow[4];
#pragma unroll
    for (int i = 0; i < 4; i++) {
        mrow[i] = -1e30f;
        lrow[i] = 0.f;
#pragma unroll
        for (int j = 0; j < 4; j++) o[i][j] = 0.f;
    }

    for (int kt = 0; kt < SQ / 64; kt++) {
        const int k0 = kt * 64;
        __syncthreads();  // protect Ks/Vs/Ps from previous iteration consumers

        // Load K and V tiles
        for (int i = tid; i < 64 * 16; i += 256) {
            int r  = i >> 4;
            int c4 = (i & 15) << 2;
            float4 kv = *(const float4*)(Kb + (size_t)(k0 + r) * DMODEL + c4);
            Ks[r * 65 + c4 + 0] = kv.x;
            Ks[r * 65 + c4 + 1] = kv.y;
            Ks[r * 65 + c4 + 2] = kv.z;
            Ks[r * 65 + c4 + 3] = kv.w;
            float4 vv = *(const float4*)(Vb + (size_t)(k0 + r) * DMODEL + c4);
            Vs[r * 65 + c4 + 0] = vv.x;
            Vs[r * 65 + c4 + 1] = vv.y;
            Vs[r * 65 + c4 + 2] = vv.z;
            Vs[r * 65 + c4 + 3] = vv.w;
        }
        __syncthreads();

        // S = Q @ K^T for this thread's 4x4 block
        float s[4][4];
#pragma unroll
        for (int i = 0; i < 4; i++)
#pragma unroll
            for (int j = 0; j < 4; j++) s[i][j] = 0.f;

#pragma unroll 8
        for (int e = 0; e < 64; e++) {
            float a[4], kv[4];
#pragma unroll
            for (int i = 0; i < 4; i++) a[i]  = Qs[(ty * 4 + i) * 65 + e];
#pragma unroll
            for (int j = 0; j < 4; j++) kv[j] = Ks[(tx * 4 + j) * 65 + e];
#pragma unroll
            for (int i = 0; i < 4; i++)
#pragma unroll
                for (int j = 0; j < 4; j++)
                    s[i][j] += a[i] * kv[j];
        }

        // scale + inverse-band mask (|qi-kj| <= WIN -> -1e9, like reference)
#pragma unroll
        for (int i = 0; i < 4; i++) {
            int qi = q0 + ty * 4 + i;
#pragma unroll
            for (int j = 0; j < 4; j++) {
                int kj = k0 + tx * 4 + j;
                float sc = s[i][j] * 0.125f;
                int dd = qi - kj;
                if (dd < 0) dd = -dd;
                if (dd <= WIN) sc = -1e9f;
                s[i][j] = sc;
            }
        }

        // Online softmax (row reductions across 16 tx lanes — stays in half-warp)
#pragma unroll
        for (int i = 0; i < 4; i++) {
            float rm = s[i][0];
            rm = fmaxf(rm, s[i][1]);
            rm = fmaxf(rm, s[i][2]);
            rm = fmaxf(rm, s[i][3]);
#pragma unroll
            for (int off = 8; off >= 1; off >>= 1)
                rm = fmaxf(rm, __shfl_xor_sync(0xffffffffu, rm, off));

            float mnew  = fmaxf(mrow[i], rm);
            float alpha = __expf(mrow[i] - mnew);
            float rs = 0.f;
#pragma unroll
            for (int j = 0; j < 4; j++) {
                float p = __expf(s[i][j] - mnew);
                Ps[(ty * 4 + i) * 65 + tx * 4 + j] = p;
                rs += p;
            }
#pragma unroll
            for (int off = 8; off >= 1; off >>= 1)
                rs += __shfl_xor_sync(0xffffffffu, rs, off);

            lrow[i] = lrow[i] * alpha + rs;
            mrow[i] = mnew;
#pragma unroll
            for (int j = 0; j < 4; j++) o[i][j] *= alpha;
        }
        __syncthreads();

        // O += P @ V
#pragma unroll 8
        for (int kk = 0; kk < 64; kk++) {
            float a[4], vv[4];
#pragma unroll
            for (int i = 0; i < 4; i++) a[i]  = Ps[(ty * 4 + i) * 65 + kk];
#pragma unroll
            for (int j = 0; j < 4; j++) vv[j] = Vs[kk * 65 + tx * 4 + j];
#pragma unroll
            for (int i = 0; i < 4; i++)
#pragma unroll
                for (int j = 0; j < 4; j++)
                    o[i][j] += a[i] * vv[j];
        }
    }

    // Write O back into [B,S,d] layout
    float* Ob = Og + (size_t)b * SQ * DMODEL + h * HDIM;
#pragma unroll
    for (int i = 0; i < 4; i++) {
        float inv_l = 1.0f / lrow[i];
        float4 c;
        c.x = o[i][0] * inv_l;
        c.y = o[i][1] * inv_l;
        c.z = o[i][2] * inv_l;
        c.w = o[i][3] * inv_l;
        *(float4*)(Ob + (size_t)(q0 + ty * 4 + i) * DMODEL + tx * 4) = c;
    }
}

// ---------------------------------------------------------------------------
// Launch
// ---------------------------------------------------------------------------
extern "C" void kernel_launch(void* const* d_in, const int* in_sizes, int n_in,
                              void* d_out, int out_size)
{
    (void)in_sizes; (void)n_in; (void)out_size;

    const float* x  = (const float*)d_in[0];
    const float* W1 = (const float*)d_in[1];
    const float* b1 = (const float*)d_in[2];
    const float* W2 = (const float*)d_in[3];
    const float* b2 = (const float*)d_in[4];
    const float* Wq = (const float*)d_in[5];
    const float* bq = (const float*)d_in[6];
    const float* Wk = (const float*)d_in[7];
    const float* bk = (const float*)d_in[8];
    const float* Wv = (const float*)d_in[9];
    const float* bv = (const float*)d_in[10];
    const float* Wo = (const float*)d_in[11];
    const float* bo = (const float*)d_in[12];
    float* out = (float*)d_out;

    float *h1, *xm, *q, *k, *v, *o;
    cudaGetSymbolAddress((void**)&h1, g_h1);
    cudaGetSymbolAddress((void**)&xm, g_xm);
    cudaGetSymbolAddress((void**)&q,  g_q);
    cudaGetSymbolAddress((void**)&k,  g_k);
    cudaGetSymbolAddress((void**)&v,  g_v);
    cudaGetSymbolAddress((void**)&o,  g_o);

    const int attn_smem = 4 * 64 * 65 * (int)sizeof(float);  // 66560 B
    cudaFuncSetAttribute(attn_kernel, cudaFuncAttributeMaxDynamicSharedMemorySize,
                         attn_smem);

    dim3 blk(256);

    // MLP layer 1: [8192,512] @ [512,1024] + b1, ReLU
    gemm_kernel<1><<<dim3(1024 / 64, TOK / 128), blk>>>(x, W1, b1, h1, TOK, 1024, DMODEL);
    // MLP layer 2: [8192,1024] @ [1024,512] + b2
    gemm_kernel<0><<<dim3(DMODEL / 64, TOK / 128), blk>>>(h1, W2, b2, xm, TOK, DMODEL, 1024);
    // Q, K, V projections
    gemm_kernel<0><<<dim3(DMODEL / 64, TOK / 128), blk>>>(xm, Wq, bq, q, TOK, DMODEL, DMODEL);
    gemm_kernel<0><<<dim3(DMODEL / 64, TOK / 128), blk>>>(xm, Wk, bk, k, TOK, DMODEL, DMODEL);
    gemm_kernel<0><<<dim3(DMODEL / 64, TOK / 128), blk>>>(xm, Wv, bv, v, TOK, DMODEL, DMODEL);
    // Attention: grid (q-tiles, B*H)
    attn_kernel<<<dim3(SQ / 64, 4 * NHEADS), blk, attn_smem>>>(q, k, v, o);
    // Output projection
    gemm_kernel<0><<<dim3(DMODEL / 64, TOK / 128), blk>>>(o, Wo, bo, out, TOK, DMODEL, DMODEL);
}

// round 2
// speedup vs baseline: 2.7043x; 2.7043x over previous
#include <cuda_runtime.h>
#include <math.h>

#define TOK    8192
#define DMODEL 512
#define SQ     2048
#define NHEADS 8
#define HDIM   64
#define WIN    5

// ---------------------------------------------------------------------------
// Device scratch
// ---------------------------------------------------------------------------
__device__ float g_h1[(size_t)TOK * 1024];
__device__ float g_xm[(size_t)TOK * DMODEL];
__device__ float g_q [(size_t)TOK * DMODEL];
__device__ float g_k [(size_t)TOK * DMODEL];
__device__ float g_v [(size_t)TOK * DMODEL];
__device__ float g_o [(size_t)TOK * DMODEL];

// ---------------------------------------------------------------------------
// Helpers: tf32 convert + m16n8k8 tf32 MMA
// ---------------------------------------------------------------------------
__device__ __forceinline__ float f2tf32(float x) {
    unsigned u;
    asm("cvt.rna.tf32.f32 %0, %1;" : "=r"(u) : "f"(x));
    return __uint_as_float(u);
}

__device__ __forceinline__ void mma_tf32(
    float& d0, float& d1, float& d2, float& d3,
    unsigned a0, unsigned a1, unsigned a2, unsigned a3,
    unsigned b0, unsigned b1)
{
    asm volatile(
        "mma.sync.aligned.m16n8k8.row.col.f32.tf32.tf32.f32 "
        "{%0,%1,%2,%3},{%4,%5,%6,%7},{%8,%9},{%0,%1,%2,%3};\n"
        : "+f"(d0), "+f"(d1), "+f"(d2), "+f"(d3)
        : "r"(a0), "r"(a1), "r"(a2), "r"(a3), "r"(b0), "r"(b1));
}

// ---------------------------------------------------------------------------
// TF32 GEMM: C[M,N] = act(A[M,K] @ B[K,N] + bias[N])
// BM=128, BN=64, BK=32. 256 threads = 8 warps (4m x 2n), warp tile 32x32.
// ---------------------------------------------------------------------------
#define APAD 36
#define BPAD 68

template<int RELU>
__global__ __launch_bounds__(256) void gemm_tf32(
    const float* __restrict__ A, const float* __restrict__ B,
    const float* __restrict__ bias, float* __restrict__ C,
    int M, int N, int K)
{
    __shared__ float As[128][APAD];  // [m][k], tf32 bit patterns
    __shared__ float Bs[32][BPAD];   // [k][n]

    const int tid  = threadIdx.x;
    const int warp = tid >> 5;
    const int lane = tid & 31;
    const int g    = lane >> 2;   // group id
    const int tg   = lane & 3;    // thread in group
    const int wm   = warp >> 1;   // 0..3
    const int wn   = warp & 1;    // 0..1
    const int m0   = blockIdx.y * 128;
    const int n0   = blockIdx.x * 64;

    float acc[2][4][4];
#pragma unroll
    for (int mi = 0; mi < 2; mi++)
#pragma unroll
        for (int nj = 0; nj < 4; nj++)
#pragma unroll
            for (int r = 0; r < 4; r++) acc[mi][nj][r] = 0.f;

    for (int k0 = 0; k0 < K; k0 += 32) {
        // A tile 128x32 -> 1024 float4 -> 4 per thread
#pragma unroll
        for (int t = 0; t < 4; t++) {
            int idx = tid + t * 256;
            int r   = idx >> 3;
            int c4  = (idx & 7) << 2;
            float4 v = *(const float4*)(A + (size_t)(m0 + r) * K + k0 + c4);
            v.x = f2tf32(v.x); v.y = f2tf32(v.y);
            v.z = f2tf32(v.z); v.w = f2tf32(v.w);
            *(float4*)&As[r][c4] = v;
        }
        // B tile 32x64 -> 512 float4 -> 2 per thread
#pragma unroll
        for (int t = 0; t < 2; t++) {
            int idx = tid + t * 256;
            int r   = idx >> 4;
            int c4  = (idx & 15) << 2;
            float4 v = *(const float4*)(B + (size_t)(k0 + r) * N + n0 + c4);
            v.x = f2tf32(v.x); v.y = f2tf32(v.y);
            v.z = f2tf32(v.z); v.w = f2tf32(v.w);
            *(float4*)&Bs[r][c4] = v;
        }
        __syncthreads();

#pragma unroll
        for (int ks = 0; ks < 4; ks++) {
            const int kb = ks * 8;
            unsigned a[2][4];
#pragma unroll
            for (int mi = 0; mi < 2; mi++) {
                int row = wm * 32 + mi * 16;
                a[mi][0] = __float_as_uint(As[row + g    ][kb + tg    ]);
                a[mi][1] = __float_as_uint(As[row + g + 8][kb + tg    ]);
                a[mi][2] = __float_as_uint(As[row + g    ][kb + tg + 4]);
                a[mi][3] = __float_as_uint(As[row + g + 8][kb + tg + 4]);
            }
            unsigned b[4][2];
#pragma unroll
            for (int nj = 0; nj < 4; nj++) {
                int col = wn * 32 + nj * 8 + g;
                b[nj][0] = __float_as_uint(Bs[kb + tg    ][col]);
                b[nj][1] = __float_as_uint(Bs[kb + tg + 4][col]);
            }
#pragma unroll
            for (int mi = 0; mi < 2; mi++)
#pragma unroll
                for (int nj = 0; nj < 4; nj++)
                    mma_tf32(acc[mi][nj][0], acc[mi][nj][1],
                             acc[mi][nj][2], acc[mi][nj][3],
                             a[mi][0], a[mi][1], a[mi][2], a[mi][3],
                             b[nj][0], b[nj][1]);
        }
        __syncthreads();
    }

    // Epilogue
#pragma unroll
    for (int mi = 0; mi < 2; mi++) {
        int row = m0 + wm * 32 + mi * 16 + g;
#pragma unroll
        for (int nj = 0; nj < 4; nj++) {
            int col = n0 + wn * 32 + nj * 8 + tg * 2;
            float2 bv = *(const float2*)(bias + col);
            float2 c0, c1;
            c0.x = acc[mi][nj][0] + bv.x;
            c0.y = acc[mi][nj][1] + bv.y;
            c1.x = acc[mi][nj][2] + bv.x;
            c1.y = acc[mi][nj][3] + bv.y;
            if (RELU) {
                c0.x = fmaxf(c0.x, 0.f); c0.y = fmaxf(c0.y, 0.f);
                c1.x = fmaxf(c1.x, 0.f); c1.y = fmaxf(c1.y, 0.f);
            }
            *(float2*)(C + (size_t)row * N + col)       = c0;
            *(float2*)(C + (size_t)(row + 8) * N + col) = c1;
        }
    }
}

// ---------------------------------------------------------------------------
// TF32 MMA flash attention, inverse band mask (|i-j| <= WIN masked out).
// Block: 128 q-rows for one (b,h). 8 warps, each warp owns 16 q-rows.
// Q fragments in registers; K,V,P tiles in dynamic smem.
// ---------------------------------------------------------------------------
#define KVPAD 68

__global__ __launch_bounds__(256) void attn_tf32(
    const float* __restrict__ Qg, const float* __restrict__ Kg,
    const float* __restrict__ Vg, float* __restrict__ Og)
{
    extern __shared__ float sm[];
    float* Ks = sm;                     // [64][KVPAD]
    float* Vs = Ks + 64 * KVPAD;        // [64][KVPAD]
    float* Ps = Vs + 64 * KVPAD;        // [128][KVPAD]  (also Q staging)

    const int tid  = threadIdx.x;
    const int warp = tid >> 5;
    const int lane = tid & 31;
    const int g    = lane >> 2;
    const int tg   = lane & 3;
    const int bh   = blockIdx.y;
    const int b    = bh >> 3;
    const int h    = bh & 7;
    const int q0   = blockIdx.x * 128;
    const int wrow = warp * 16;         // warp's q-row base within tile

    const float* Qb = Qg + (size_t)b * SQ * DMODEL + h * HDIM;
    const float* Kb = Kg + (size_t)b * SQ * DMODEL + h * HDIM;
    const float* Vb = Vg + (size_t)b * SQ * DMODEL + h * HDIM;

    // Stage Q tile (128x64) into Ps, converted to tf32
#pragma unroll
    for (int t = 0; t < 8; t++) {
        int idx = tid + t * 256;        // 0..2047 float4s
        int r   = idx >> 4;
        int c4  = (idx & 15) << 2;
        float4 v = *(const float4*)(Qb + (size_t)(q0 + r) * DMODEL + c4);
        v.x = f2tf32(v.x); v.y = f2tf32(v.y);
        v.z = f2tf32(v.z); v.w = f2tf32(v.w);
        *(float4*)&Ps[r * KVPAD + c4] = v;
    }
    __syncthreads();

    // Q fragments: 8 k-steps (head dim 64), 4 regs each
    unsigned qf[8][4];
#pragma unroll
    for (int ks = 0; ks < 8; ks++) {
        int kb = ks * 8;
        qf[ks][0] = __float_as_uint(Ps[(wrow + g    ) * KVPAD + kb + tg    ]);
        qf[ks][1] = __float_as_uint(Ps[(wrow + g + 8) * KVPAD + kb + tg    ]);
        qf[ks][2] = __float_as_uint(Ps[(wrow + g    ) * KVPAD + kb + tg + 4]);
        qf[ks][3] = __float_as_uint(Ps[(wrow + g + 8) * KVPAD + kb + tg + 4]);
    }

    float oacc[8][4];
#pragma unroll
    for (int nj = 0; nj < 8; nj++)
#pragma unroll
        for (int r = 0; r < 4; r++) oacc[nj][r] = 0.f;
    float mrow[2] = { -1e30f, -1e30f };
    float lrow[2] = { 0.f, 0.f };

    for (int kt = 0; kt < SQ / 64; kt++) {
        const int k0 = kt * 64;
        __syncthreads();   // previous iteration's consumers of Ks/Vs done

        // Load K and V tiles (64x64 each), 4 float4 per thread per tensor
#pragma unroll
        for (int t = 0; t < 4; t++) {
            int idx = tid + t * 256;
            int r   = idx >> 4;
            int c4  = (idx & 15) << 2;
            float4 kv = *(const float4*)(Kb + (size_t)(k0 + r) * DMODEL + c4);
            kv.x = f2tf32(kv.x); kv.y = f2tf32(kv.y);
            kv.z = f2tf32(kv.z); kv.w = f2tf32(kv.w);
            *(float4*)&Ks[r * KVPAD + c4] = kv;
            float4 vv = *(const float4*)(Vb + (size_t)(k0 + r) * DMODEL + c4);
            vv.x = f2tf32(vv.x); vv.y = f2tf32(vv.y);
            vv.z = f2tf32(vv.z); vv.w = f2tf32(vv.w);
            *(float4*)&Vs[r * KVPAD + c4] = vv;
        }
        __syncthreads();

        // S = Q @ K^T : sfrag[8 key-tiles][4]
        float sfrag[8][4];
#pragma unroll
        for (int nj = 0; nj < 8; nj++)
#pragma unroll
            for (int r = 0; r < 4; r++) sfrag[nj][r] = 0.f;

#pragma unroll
        for (int ks = 0; ks < 8; ks++) {
            int kb = ks * 8;
            unsigned bq[8][2];
#pragma unroll
            for (int nj = 0; nj < 8; nj++) {
                int key = nj * 8 + g;
                bq[nj][0] = __float_as_uint(Ks[key * KVPAD + kb + tg    ]);
                bq[nj][1] = __float_as_uint(Ks[key * KVPAD + kb + tg + 4]);
            }
#pragma unroll
            for (int nj = 0; nj < 8; nj++)
                mma_tf32(sfrag[nj][0], sfrag[nj][1], sfrag[nj][2], sfrag[nj][3],
                         qf[ks][0], qf[ks][1], qf[ks][2], qf[ks][3],
                         bq[nj][0], bq[nj][1]);
        }

        // Scale + inverse-band mask
        const int qr0 = q0 + wrow + g;       // row for regs 0,1
        const int qr1 = qr0 + 8;             // row for regs 2,3
        const bool need_mask = (k0 <= q0 + 127 + WIN) && (k0 + 63 >= q0 - WIN);
#pragma unroll
        for (int nj = 0; nj < 8; nj++) {
            int kc0 = k0 + nj * 8 + tg * 2;
            float s0 = sfrag[nj][0] * 0.125f;
            float s1 = sfrag[nj][1] * 0.125f;
            float s2 = sfrag[nj][2] * 0.125f;
            float s3 = sfrag[nj][3] * 0.125f;
            if (need_mask) {
                if (abs(qr0 - kc0)     <= WIN) s0 = -1e9f;
                if (abs(qr0 - kc0 - 1) <= WIN) s1 = -1e9f;
                if (abs(qr1 - kc0)     <= WIN) s2 = -1e9f;
                if (abs(qr1 - kc0 - 1) <= WIN) s3 = -1e9f;
            }
            sfrag[nj][0] = s0; sfrag[nj][1] = s1;
            sfrag[nj][2] = s2; sfrag[nj][3] = s3;
        }

        // Online softmax for the 2 rows this lane covers
        float tmax0 = -1e30f, tmax1 = -1e30f;
#pragma unroll
        for (int nj = 0; nj < 8; nj++) {
            tmax0 = fmaxf(tmax0, fmaxf(sfrag[nj][0], sfrag[nj][1]));
            tmax1 = fmaxf(tmax1, fmaxf(sfrag[nj][2], sfrag[nj][3]));
        }
#pragma unroll
        for (int off = 1; off <= 2; off <<= 1) {
            tmax0 = fmaxf(tmax0, __shfl_xor_sync(0xffffffffu, tmax0, off));
            tmax1 = fmaxf(tmax1, __shfl_xor_sync(0xffffffffu, tmax1, off));
        }
        float mnew0 = fmaxf(mrow[0], tmax0);
        float mnew1 = fmaxf(mrow[1], tmax1);
        float alpha0 = __expf(mrow[0] - mnew0);
        float alpha1 = __expf(mrow[1] - mnew1);

        float rs0 = 0.f, rs1 = 0.f;
#pragma unroll
        for (int nj = 0; nj < 8; nj++) {
            float p0 = __expf(sfrag[nj][0] - mnew0);
            float p1 = __expf(sfrag[nj][1] - mnew0);
            float p2 = __expf(sfrag[nj][2] - mnew1);
            float p3 = __expf(sfrag[nj][3] - mnew1);
            rs0 += p0 + p1;
            rs1 += p2 + p3;
            int kc = nj * 8 + tg * 2;
            Ps[(wrow + g    ) * KVPAD + kc    ] = f2tf32(p0);
            Ps[(wrow + g    ) * KVPAD + kc + 1] = f2tf32(p1);
            Ps[(wrow + g + 8) * KVPAD + kc    ] = f2tf32(p2);
            Ps[(wrow + g + 8) * KVPAD + kc + 1] = f2tf32(p3);
        }
#pragma unroll
        for (int off = 1; off <= 2; off <<= 1) {
            rs0 += __shfl_xor_sync(0xffffffffu, rs0, off);
            rs1 += __shfl_xor_sync(0xffffffffu, rs1, off);
        }
        lrow[0] = lrow[0] * alpha0 + rs0;
        lrow[1] = lrow[1] * alpha1 + rs1;
        mrow[0] = mnew0;
        mrow[1] = mnew1;
#pragma unroll
        for (int nj = 0; nj < 8; nj++) {
            oacc[nj][0] *= alpha0; oacc[nj][1] *= alpha0;
            oacc[nj][2] *= alpha1; oacc[nj][3] *= alpha1;
        }
        __syncwarp();

        // O += P @ V  (P: warp-private 16 rows; V: [key][d])
#pragma unroll
        for (int ks = 0; ks < 8; ks++) {
            int kb = ks * 8;
            unsigned ap[4];
            ap[0] = __float_as_uint(Ps[(wrow + g    ) * KVPAD + kb + tg    ]);
            ap[1] = __float_as_uint(Ps[(wrow + g + 8) * KVPAD + kb + tg    ]);
            ap[2] = __float_as_uint(Ps[(wrow + g    ) * KVPAD + kb + tg + 4]);
            ap[3] = __float_as_uint(Ps[(wrow + g + 8) * KVPAD + kb + tg + 4]);
#pragma unroll
            for (int nj = 0; nj < 8; nj++) {
                unsigned bv0 = __float_as_uint(Vs[(kb + tg    ) * KVPAD + nj * 8 + g]);
                unsigned bv1 = __float_as_uint(Vs[(kb + tg + 4) * KVPAD + nj * 8 + g]);
                mma_tf32(oacc[nj][0], oacc[nj][1], oacc[nj][2], oacc[nj][3],
                         ap[0], ap[1], ap[2], ap[3], bv0, bv1);
            }
        }
    }

    // Finalize and store
    float inv0 = 1.0f / lrow[0];
    float inv1 = 1.0f / lrow[1];
    float* Ob = Og + (size_t)b * SQ * DMODEL + h * HDIM;
    const int row0 = q0 + wrow + g;
#pragma unroll
    for (int nj = 0; nj < 8; nj++) {
        int col = nj * 8 + tg * 2;
        float2 c0, c1;
        c0.x = oacc[nj][0] * inv0; c0.y = oacc[nj][1] * inv0;
        c1.x = oacc[nj][2] * inv1; c1.y = oacc[nj][3] * inv1;
        *(float2*)(Ob + (size_t)row0 * DMODEL + col)       = c0;
        *(float2*)(Ob + (size_t)(row0 + 8) * DMODEL + col) = c1;
    }
}

// ---------------------------------------------------------------------------
// Launch
// ---------------------------------------------------------------------------
extern "C" void kernel_launch(void* const* d_in, const int* in_sizes, int n_in,
                              void* d_out, int out_size)
{
    (void)in_sizes; (void)n_in; (void)out_size;

    const float* x  = (const float*)d_in[0];
    const float* W1 = (const float*)d_in[1];
    const float* b1 = (const float*)d_in[2];
    const float* W2 = (const float*)d_in[3];
    const float* b2 = (const float*)d_in[4];
    const float* Wq = (const float*)d_in[5];
    const float* bq = (const float*)d_in[6];
    const float* Wk = (const float*)d_in[7];
    const float* bk = (const float*)d_in[8];
    const float* Wv = (const float*)d_in[9];
    const float* bv = (const float*)d_in[10];
    const float* Wo = (const float*)d_in[11];
    const float* bo = (const float*)d_in[12];
    float* out = (float*)d_out;

    float *h1, *xm, *q, *k, *v, *o;
    cudaGetSymbolAddress((void**)&h1, g_h1);
    cudaGetSymbolAddress((void**)&xm, g_xm);
    cudaGetSymbolAddress((void**)&q,  g_q);
    cudaGetSymbolAddress((void**)&k,  g_k);
    cudaGetSymbolAddress((void**)&v,  g_v);
    cudaGetSymbolAddress((void**)&o,  g_o);

    const int attn_smem = (64 + 64 + 128) * KVPAD * (int)sizeof(float); // 69632
    cudaFuncSetAttribute(attn_tf32, cudaFuncAttributeMaxDynamicSharedMemorySize,
                         attn_smem);

    dim3 blk(256);

    gemm_tf32<1><<<dim3(1024 / 64, TOK / 128), blk>>>(x,  W1, b1, h1,  TOK, 1024,  DMODEL);
    gemm_tf32<0><<<dim3(DMODEL / 64, TOK / 128), blk>>>(h1, W2, b2, xm, TOK, DMODEL, 1024);
    gemm_tf32<0><<<dim3(DMODEL / 64, TOK / 128), blk>>>(xm, Wq, bq, q,  TOK, DMODEL, DMODEL);
    gemm_tf32<0><<<dim3(DMODEL / 64, TOK / 128), blk>>>(xm, Wk, bk, k,  TOK, DMODEL, DMODEL);
    gemm_tf32<0><<<dim3(DMODEL / 64, TOK / 128), blk>>>(xm, Wv, bv, v,  TOK, DMODEL, DMODEL);
    attn_tf32<<<dim3(SQ / 128, 4 * NHEADS), blk, attn_smem>>>(q, k, v, o);
    gemm_tf32<0><<<dim3(DMODEL / 64, TOK / 128), blk>>>(o,  Wo, bo, out, TOK, DMODEL, DMODEL);
}

// round 3
// speedup vs baseline: 3.6251x; 1.3405x over previous
#include <cuda_runtime.h>
#include <math.h>

#define TOK    8192
#define DMODEL 512
#define SQ     2048
#define NHEADS 8
#define HDIM   64
#define WIN    5

// ---------------------------------------------------------------------------
// Device scratch
// ---------------------------------------------------------------------------
__device__ float g_h1[(size_t)TOK * 1024];
__device__ float g_xm[(size_t)TOK * DMODEL];
__device__ float g_q [(size_t)TOK * DMODEL];
__device__ float g_k [(size_t)TOK * DMODEL];
__device__ float g_v [(size_t)TOK * DMODEL];
__device__ float g_o [(size_t)TOK * DMODEL];

// ---------------------------------------------------------------------------
// tf32 helpers
// ---------------------------------------------------------------------------
__device__ __forceinline__ float f2tf32(float x) {
    unsigned u;
    asm("cvt.rna.tf32.f32 %0, %1;" : "=r"(u) : "f"(x));
    return __uint_as_float(u);
}

__device__ __forceinline__ void mma_tf32(
    float& d0, float& d1, float& d2, float& d3,
    unsigned a0, unsigned a1, unsigned a2, unsigned a3,
    unsigned b0, unsigned b1)
{
    asm volatile(
        "mma.sync.aligned.m16n8k8.row.col.f32.tf32.tf32.f32 "
        "{%0,%1,%2,%3},{%4,%5,%6,%7},{%8,%9},{%0,%1,%2,%3};\n"
        : "+f"(d0), "+f"(d1), "+f"(d2), "+f"(d3)
        : "r"(a0), "r"(a1), "r"(a2), "r"(a3), "r"(b0), "r"(b1));
}

// ---------------------------------------------------------------------------
// TF32 GEMM v2: C[M,N] = act(A @ B + bias)
// BM=128, BN=128, BK=16; 128 threads = 4 warps (2x2), warp tile 64x64.
// Register-staged double buffering, 1 sync per k-iteration.
// ---------------------------------------------------------------------------
#define APAD 20    // 16+4: bank-conflict-free a-frag loads
#define BPAD 136   // 128+8: bank-conflict-free b-frag loads

template<int RELU>
__global__ __launch_bounds__(128) void gemm_tf32(
    const float* __restrict__ A, const float* __restrict__ B,
    const float* __restrict__ bias, float* __restrict__ C,
    int M, int N, int K)
{
    __shared__ float As[2][128][APAD];   // [buf][m][k] tf32 bits
    __shared__ float Bs[2][16][BPAD];    // [buf][k][n]

    const int tid  = threadIdx.x;
    const int warp = tid >> 5;
    const int lane = tid & 31;
    const int g    = lane >> 2;
    const int tg   = lane & 3;
    const int wm   = warp >> 1;          // 0..1
    const int wn   = warp & 1;           // 0..1
    const int m0   = blockIdx.y * 128;
    const int n0   = blockIdx.x * 128;

    // per-thread load coords
    const int ar = tid >> 2;             // base row for A loads (stride 32 over t)
    const int ac = (tid & 3) << 2;
    const int br = tid >> 5;             // base row for B loads (stride 4 over t)
    const int bc = (tid & 31) << 2;

    float acc[4][8][4];
#pragma unroll
    for (int mi = 0; mi < 4; mi++)
#pragma unroll
        for (int nj = 0; nj < 8; nj++)
#pragma unroll
            for (int r = 0; r < 4; r++) acc[mi][nj][r] = 0.f;

    float4 ra[4], rb[4];

    // Load tile 0 into regs
#pragma unroll
    for (int t = 0; t < 4; t++) {
        ra[t] = *(const float4*)(A + (size_t)(m0 + ar + t * 32) * K + ac);
        rb[t] = *(const float4*)(B + (size_t)(br + t * 4) * N + n0 + bc);
    }
    // cvt + store buf 0
#pragma unroll
    for (int t = 0; t < 4; t++) {
        float4 v = ra[t];
        v.x = f2tf32(v.x); v.y = f2tf32(v.y); v.z = f2tf32(v.z); v.w = f2tf32(v.w);
        *(float4*)&As[0][ar + t * 32][ac] = v;
        float4 w = rb[t];
        w.x = f2tf32(w.x); w.y = f2tf32(w.y); w.z = f2tf32(w.z); w.w = f2tf32(w.w);
        *(float4*)&Bs[0][br + t * 4][bc] = w;
    }
    __syncthreads();

    const int nt = K >> 4;
    int buf = 0;

    for (int kt = 0; kt < nt; kt++) {
        const bool more = (kt + 1 < nt);
        if (more) {
            const int k0 = (kt + 1) << 4;
#pragma unroll
            for (int t = 0; t < 4; t++) {
                ra[t] = *(const float4*)(A + (size_t)(m0 + ar + t * 32) * K + k0 + ac);
                rb[t] = *(const float4*)(B + (size_t)(k0 + br + t * 4) * N + n0 + bc);
            }
        }

        // Compute from As[buf], Bs[buf]
#pragma unroll
        for (int ks = 0; ks < 2; ks++) {
            const int kb = ks * 8;
            unsigned a[4][4];
#pragma unroll
            for (int mi = 0; mi < 4; mi++) {
                const int row = wm * 64 + mi * 16;
                a[mi][0] = __float_as_uint(As[buf][row + g    ][kb + tg    ]);
                a[mi][1] = __float_as_uint(As[buf][row + g + 8][kb + tg    ]);
                a[mi][2] = __float_as_uint(As[buf][row + g    ][kb + tg + 4]);
                a[mi][3] = __float_as_uint(As[buf][row + g + 8][kb + tg + 4]);
            }
            unsigned b[8][2];
#pragma unroll
            for (int nj = 0; nj < 8; nj++) {
                const int col = wn * 64 + nj * 8 + g;
                b[nj][0] = __float_as_uint(Bs[buf][kb + tg    ][col]);
                b[nj][1] = __float_as_uint(Bs[buf][kb + tg + 4][col]);
            }
#pragma unroll
            for (int mi = 0; mi < 4; mi++)
#pragma unroll
                for (int nj = 0; nj < 8; nj++)
                    mma_tf32(acc[mi][nj][0], acc[mi][nj][1],
                             acc[mi][nj][2], acc[mi][nj][3],
                             a[mi][0], a[mi][1], a[mi][2], a[mi][3],
                             b[nj][0], b[nj][1]);
        }

        if (more) {
            const int nb = buf ^ 1;
#pragma unroll
            for (int t = 0; t < 4; t++) {
                float4 v = ra[t];
                v.x = f2tf32(v.x); v.y = f2tf32(v.y); v.z = f2tf32(v.z); v.w = f2tf32(v.w);
                *(float4*)&As[nb][ar + t * 32][ac] = v;
                float4 w = rb[t];
                w.x = f2tf32(w.x); w.y = f2tf32(w.y); w.z = f2tf32(w.z); w.w = f2tf32(w.w);
                *(float4*)&Bs[nb][br + t * 4][bc] = w;
            }
            __syncthreads();
            buf = nb;
        }
    }

    // Epilogue
#pragma unroll
    for (int mi = 0; mi < 4; mi++) {
        const int row = m0 + wm * 64 + mi * 16 + g;
#pragma unroll
        for (int nj = 0; nj < 8; nj++) {
            const int col = n0 + wn * 64 + nj * 8 + tg * 2;
            float2 bv = *(const float2*)(bias + col);
            float2 c0, c1;
            c0.x = acc[mi][nj][0] + bv.x;
            c0.y = acc[mi][nj][1] + bv.y;
            c1.x = acc[mi][nj][2] + bv.x;
            c1.y = acc[mi][nj][3] + bv.y;
            if (RELU) {
                c0.x = fmaxf(c0.x, 0.f); c0.y = fmaxf(c0.y, 0.f);
                c1.x = fmaxf(c1.x, 0.f); c1.y = fmaxf(c1.y, 0.f);
            }
            *(float2*)(C + (size_t)row * N + col)       = c0;
            *(float2*)(C + (size_t)(row + 8) * N + col) = c1;
        }
    }
}

// ---------------------------------------------------------------------------
// TF32 MMA flash attention v2, inverse band mask.
// Block: 128 q-rows for one (b,h), 128 threads = 4 warps.
// Warp tile: 32 q-rows x 64 keys (mi=2). Q pre-scaled by 1/8.
// ---------------------------------------------------------------------------
#define QKP 68   // pad for Qs/Ks/Ps (4 mod 32)
#define VP  72   // pad for Vs (8 mod 32)

__global__ __launch_bounds__(128) void attn_tf32(
    const float* __restrict__ Qg, const float* __restrict__ Kg,
    const float* __restrict__ Vg, float* __restrict__ Og)
{
    extern __shared__ float sm[];
    float* Qs = sm;                       // [128][QKP]
    float* Ks = Qs + 128 * QKP;           // [64][QKP]
    float* Ps = Ks + 64 * QKP;            // [128][QKP]
    float* Vs = Ps + 128 * QKP;           // [64][VP]

    const int tid  = threadIdx.x;
    const int warp = tid >> 5;
    const int lane = tid & 31;
    const int g    = lane >> 2;
    const int tg   = lane & 3;
    const int bh   = blockIdx.y;
    const int b    = bh >> 3;
    const int h    = bh & 7;
    const int q0   = blockIdx.x * 128;
    const int wrow = warp * 32;

    const float* Qb = Qg + (size_t)b * SQ * DMODEL + h * HDIM;
    const float* Kb = Kg + (size_t)b * SQ * DMODEL + h * HDIM;
    const float* Vb = Vg + (size_t)b * SQ * DMODEL + h * HDIM;

    // Stage Q tile (128x64), pre-scaled by 1/8, tf32
#pragma unroll
    for (int t = 0; t < 16; t++) {
        int idx = tid + t * 128;
        int r   = idx >> 4;
        int c4  = (idx & 15) << 2;
        float4 v = *(const float4*)(Qb + (size_t)(q0 + r) * DMODEL + c4);
        v.x = f2tf32(v.x * 0.125f); v.y = f2tf32(v.y * 0.125f);
        v.z = f2tf32(v.z * 0.125f); v.w = f2tf32(v.w * 0.125f);
        *(float4*)&Qs[r * QKP + c4] = v;
    }

    float oacc[2][8][4];
#pragma unroll
    for (int mi = 0; mi < 2; mi++)
#pragma unroll
        for (int nj = 0; nj < 8; nj++)
#pragma unroll
            for (int r = 0; r < 4; r++) oacc[mi][nj][r] = 0.f;
    float mrow[2][2], lrow[2][2];
#pragma unroll
    for (int mi = 0; mi < 2; mi++) {
        mrow[mi][0] = mrow[mi][1] = -1e30f;
        lrow[mi][0] = lrow[mi][1] = 0.f;
    }

    for (int kt = 0; kt < SQ / 64; kt++) {
        const int k0 = kt * 64;
        __syncthreads();   // Qs visible (kt=0) / prev Ks,Vs,Ps consumers done

        // Load K and V tiles (64x64 each)
#pragma unroll
        for (int t = 0; t < 8; t++) {
            int idx = tid + t * 128;
            int r   = idx >> 4;
            int c4  = (idx & 15) << 2;
            float4 kv = *(const float4*)(Kb + (size_t)(k0 + r) * DMODEL + c4);
            kv.x = f2tf32(kv.x); kv.y = f2tf32(kv.y);
            kv.z = f2tf32(kv.z); kv.w = f2tf32(kv.w);
            *(float4*)&Ks[r * QKP + c4] = kv;
            float4 vv = *(const float4*)(Vb + (size_t)(k0 + r) * DMODEL + c4);
            vv.x = f2tf32(vv.x); vv.y = f2tf32(vv.y);
            vv.z = f2tf32(vv.z); vv.w = f2tf32(vv.w);
            *(float4*)&Vs[r * VP + c4] = vv;
        }
        __syncthreads();

        // S = Qs @ Ks^T  (32x64 per warp)
        float sfrag[2][8][4];
#pragma unroll
        for (int mi = 0; mi < 2; mi++)
#pragma unroll
            for (int nj = 0; nj < 8; nj++)
#pragma unroll
                for (int r = 0; r < 4; r++) sfrag[mi][nj][r] = 0.f;

#pragma unroll
        for (int ks = 0; ks < 8; ks++) {
            const int kb = ks * 8;
            unsigned a[2][4];
#pragma unroll
            for (int mi = 0; mi < 2; mi++) {
                const int row = wrow + mi * 16;
                a[mi][0] = __float_as_uint(Qs[(row + g    ) * QKP + kb + tg    ]);
                a[mi][1] = __float_as_uint(Qs[(row + g + 8) * QKP + kb + tg    ]);
                a[mi][2] = __float_as_uint(Qs[(row + g    ) * QKP + kb + tg + 4]);
                a[mi][3] = __float_as_uint(Qs[(row + g + 8) * QKP + kb + tg + 4]);
            }
            unsigned bq[8][2];
#pragma unroll
            for (int nj = 0; nj < 8; nj++) {
                const int key = nj * 8 + g;
                bq[nj][0] = __float_as_uint(Ks[key * QKP + kb + tg    ]);
                bq[nj][1] = __float_as_uint(Ks[key * QKP + kb + tg + 4]);
            }
#pragma unroll
            for (int mi = 0; mi < 2; mi++)
#pragma unroll
                for (int nj = 0; nj < 8; nj++)
                    mma_tf32(sfrag[mi][nj][0], sfrag[mi][nj][1],
                             sfrag[mi][nj][2], sfrag[mi][nj][3],
                             a[mi][0], a[mi][1], a[mi][2], a[mi][3],
                             bq[nj][0], bq[nj][1]);
        }

        // Inverse-band mask (Q already scaled)
        const bool need_mask = (k0 <= q0 + 127 + WIN) && (k0 + 63 >= q0 - WIN);
        if (need_mask) {
#pragma unroll
            for (int mi = 0; mi < 2; mi++) {
                const int qr0 = q0 + wrow + mi * 16 + g;
                const int qr1 = qr0 + 8;
#pragma unroll
                for (int nj = 0; nj < 8; nj++) {
                    const int kc0 = k0 + nj * 8 + tg * 2;
                    int d;
                    d = qr0 - kc0;     if (d < 0) d = -d; if (d <= WIN) sfrag[mi][nj][0] = -1e9f;
                    d = qr0 - kc0 - 1; if (d < 0) d = -d; if (d <= WIN) sfrag[mi][nj][1] = -1e9f;
                    d = qr1 - kc0;     if (d < 0) d = -d; if (d <= WIN) sfrag[mi][nj][2] = -1e9f;
                    d = qr1 - kc0 - 1; if (d < 0) d = -d; if (d <= WIN) sfrag[mi][nj][3] = -1e9f;
                }
            }
        }

        // Online softmax (row reduce over tg group: xor 1,2)
#pragma unroll
        for (int mi = 0; mi < 2; mi++) {
            float tmax0 = -1e30f, tmax1 = -1e30f;
#pragma unroll
            for (int nj = 0; nj < 8; nj++) {
                tmax0 = fmaxf(tmax0, fmaxf(sfrag[mi][nj][0], sfrag[mi][nj][1]));
                tmax1 = fmaxf(tmax1, fmaxf(sfrag[mi][nj][2], sfrag[mi][nj][3]));
            }
#pragma unroll
            for (int off = 1; off <= 2; off <<= 1) {
                tmax0 = fmaxf(tmax0, __shfl_xor_sync(0xffffffffu, tmax0, off));
                tmax1 = fmaxf(tmax1, __shfl_xor_sync(0xffffffffu, tmax1, off));
            }
            const float mnew0 = fmaxf(mrow[mi][0], tmax0);
            const float mnew1 = fmaxf(mrow[mi][1], tmax1);
            const float alpha0 = __expf(mrow[mi][0] - mnew0);
            const float alpha1 = __expf(mrow[mi][1] - mnew1);

            float rs0 = 0.f, rs1 = 0.f;
            const int prow0 = (wrow + mi * 16 + g) * QKP;
            const int prow1 = (wrow + mi * 16 + g + 8) * QKP;
#pragma unroll
            for (int nj = 0; nj < 8; nj++) {
                const float p0 = __expf(sfrag[mi][nj][0] - mnew0);
                const float p1 = __expf(sfrag[mi][nj][1] - mnew0);
                const float p2 = __expf(sfrag[mi][nj][2] - mnew1);
                const float p3 = __expf(sfrag[mi][nj][3] - mnew1);
                rs0 += p0 + p1;
                rs1 += p2 + p3;
                const int kc = nj * 8 + tg * 2;
                Ps[prow0 + kc    ] = f2tf32(p0);
                Ps[prow0 + kc + 1] = f2tf32(p1);
                Ps[prow1 + kc    ] = f2tf32(p2);
                Ps[prow1 + kc + 1] = f2tf32(p3);
            }
#pragma unroll
            for (int off = 1; off <= 2; off <<= 1) {
                rs0 += __shfl_xor_sync(0xffffffffu, rs0, off);
                rs1 += __shfl_xor_sync(0xffffffffu, rs1, off);
            }
            lrow[mi][0] = lrow[mi][0] * alpha0 + rs0;
            lrow[mi][1] = lrow[mi][1] * alpha1 + rs1;
            mrow[mi][0] = mnew0;
            mrow[mi][1] = mnew1;
#pragma unroll
            for (int nj = 0; nj < 8; nj++) {
                oacc[mi][nj][0] *= alpha0; oacc[mi][nj][1] *= alpha0;
                oacc[mi][nj][2] *= alpha1; oacc[mi][nj][3] *= alpha1;
            }
        }
        __syncwarp();

        // O += P @ V
#pragma unroll
        for (int ks = 0; ks < 8; ks++) {
            const int kb = ks * 8;
            unsigned ap[2][4];
#pragma unroll
            for (int mi = 0; mi < 2; mi++) {
                const int row = wrow + mi * 16;
                ap[mi][0] = __float_as_uint(Ps[(row + g    ) * QKP + kb + tg    ]);
                ap[mi][1] = __float_as_uint(Ps[(row + g + 8) * QKP + kb + tg    ]);
                ap[mi][2] = __float_as_uint(Ps[(row + g    ) * QKP + kb + tg + 4]);
                ap[mi][3] = __float_as_uint(Ps[(row + g + 8) * QKP + kb + tg + 4]);
            }
            unsigned bv[8][2];
#pragma unroll
            for (int nj = 0; nj < 8; nj++) {
                const int col = nj * 8 + g;
                bv[nj][0] = __float_as_uint(Vs[(kb + tg    ) * VP + col]);
                bv[nj][1] = __float_as_uint(Vs[(kb + tg + 4) * VP + col]);
            }
#pragma unroll
            for (int mi = 0; mi < 2; mi++)
#pragma unroll
                for (int nj = 0; nj < 8; nj++)
                    mma_tf32(oacc[mi][nj][0], oacc[mi][nj][1],
                             oacc[mi][nj][2], oacc[mi][nj][3],
                             ap[mi][0], ap[mi][1], ap[mi][2], ap[mi][3],
                             bv[nj][0], bv[nj][1]);
        }
    }

    // Finalize and store
    float* Ob = Og + (size_t)b * SQ * DMODEL + h * HDIM;
#pragma unroll
    for (int mi = 0; mi < 2; mi++) {
        const float inv0 = 1.0f / lrow[mi][0];
        const float inv1 = 1.0f / lrow[mi][1];
        const int row0 = q0 + wrow + mi * 16 + g;
#pragma unroll
        for (int nj = 0; nj < 8; nj++) {
            const int col = nj * 8 + tg * 2;
            float2 c0, c1;
            c0.x = oacc[mi][nj][0] * inv0; c0.y = oacc[mi][nj][1] * inv0;
            c1.x = oacc[mi][nj][2] * inv1; c1.y = oacc[mi][nj][3] * inv1;
            *(float2*)(Ob + (size_t)row0 * DMODEL + col)       = c0;
            *(float2*)(Ob + (size_t)(row0 + 8) * DMODEL + col) = c1;
        }
    }
}

// ---------------------------------------------------------------------------
// Launch
// ---------------------------------------------------------------------------
extern "C" void kernel_launch(void* const* d_in, const int* in_sizes, int n_in,
                              void* d_out, int out_size)
{
    (void)in_sizes; (void)n_in; (void)out_size;

    const float* x  = (const float*)d_in[0];
    const float* W1 = (const float*)d_in[1];
    const float* b1 = (const float*)d_in[2];
    const float* W2 = (const float*)d_in[3];
    const float* b2 = (const float*)d_in[4];
    const float* Wq = (const float*)d_in[5];
    const float* bq = (const float*)d_in[6];
    const float* Wk = (const float*)d_in[7];
    const float* bk = (const float*)d_in[8];
    const float* Wv = (const float*)d_in[9];
    const float* bv = (const float*)d_in[10];
    const float* Wo = (const float*)d_in[11];
    const float* bo = (const float*)d_in[12];
    float* out = (float*)d_out;

    float *h1, *xm, *q, *k, *v, *o;
    cudaGetSymbolAddress((void**)&h1, g_h1);
    cudaGetSymbolAddress((void**)&xm, g_xm);
    cudaGetSymbolAddress((void**)&q,  g_q);
    cudaGetSymbolAddress((void**)&k,  g_k);
    cudaGetSymbolAddress((void**)&v,  g_v);
    cudaGetSymbolAddress((void**)&o,  g_o);

    const int attn_smem = ((128 + 64 + 128) * QKP + 64 * VP) * (int)sizeof(float); // 105472
    cudaFuncSetAttribute(attn_tf32, cudaFuncAttributeMaxDynamicSharedMemorySize,
                         attn_smem);

    dim3 blk(128);

    gemm_tf32<1><<<dim3(1024 / 128, TOK / 128), blk>>>(x,  W1, b1, h1,  TOK, 1024,  DMODEL);
    gemm_tf32<0><<<dim3(DMODEL / 128, TOK / 128), blk>>>(h1, W2, b2, xm, TOK, DMODEL, 1024);
    gemm_tf32<0><<<dim3(DMODEL / 128, TOK / 128), blk>>>(xm, Wq, bq, q,  TOK, DMODEL, DMODEL);
    gemm_tf32<0><<<dim3(DMODEL / 128, TOK / 128), blk>>>(xm, Wk, bk, k,  TOK, DMODEL, DMODEL);
    gemm_tf32<0><<<dim3(DMODEL / 128, TOK / 128), blk>>>(xm, Wv, bv, v,  TOK, DMODEL, DMODEL);
    attn_tf32<<<dim3(SQ / 128, 4 * NHEADS), blk, attn_smem>>>(q, k, v, o);
    gemm_tf32<0><<<dim3(DMODEL / 128, TOK / 128), blk>>>(o,  Wo, bo, out, TOK, DMODEL, DMODEL);
}